// round 8
// baseline (speedup 1.0000x reference)
#include <cuda_runtime.h>
#include <cuda_fp16.h>
#include <cstdint>

// Fused QKV projection: X[16384,1024] @ [Wq|Wk|Wv][1024,3072] + bias,
// head-split epilogue. fp16 mma.sync.m16n8k16 (fp32 accum).
//
// R8: A fragments are fetched straight from g_A via LDG.128 (g_A is already
// in fragment order) — no STS/LDS for A at all. Shared memory holds only the
// B stages (4 x 8KB), so the smem crossbar load halves and the L1D carveout
// grows to ~132KB, caching the pair-warp A re-reads.
// GEMM: CTA 128x128, 4 warps (2x2 of 64x64), BK=32, 4-stage cp.async for B.

#define MDIM 16384
#define KDIM 1024
#define NTOT 3072
#define BM 128
#define BN 128
#define BK 32
#define NKT (KDIM / BK)          // 32
#define NSTAGE 4
#define B_BYTES 8192             // 2 nbL x 2 kc x 4 c x 512B
#define SMEM_TOTAL (NSTAGE * B_BYTES)   // 32768
#define OUT_PER_MAT (4 * 16 * 4096 * 64)

__device__ uint4 g_A[(size_t)1024 * 64 * 32];      // 32 MB
__device__ uint4 g_B[(size_t)48 * 64 * 4 * 32];    // 6 MB

__device__ __forceinline__ uint32_t h2u(float a, float b) {
    __half2 h = __float22half2_rn(make_float2(a, b));
    return *reinterpret_cast<uint32_t*>(&h);
}
__device__ __forceinline__ uint32_t smem_u32(const void* p) {
    uint32_t a;
    asm("{ .reg .u64 t; cvta.to.shared.u64 t, %1; cvt.u32.u64 %0, t; }" : "=r"(a) : "l"(p));
    return a;
}
__device__ __forceinline__ void cp16(uint32_t dst, const void* src) {
    asm volatile("cp.async.cg.shared.global [%0], [%1], 16;" :: "r"(dst), "l"(src));
}
__device__ __forceinline__ void mma_f16(float* c, const uint4& a, uint32_t b0, uint32_t b1) {
    asm volatile(
        "mma.sync.aligned.m16n8k16.row.col.f32.f16.f16.f32 "
        "{%0,%1,%2,%3},{%4,%5,%6,%7},{%8,%9},{%0,%1,%2,%3};"
        : "+f"(c[0]), "+f"(c[1]), "+f"(c[2]), "+f"(c[3])
        : "r"(a.x), "r"(a.y), "r"(a.z), "r"(a.w), "r"(b0), "r"(b1));
}

// ---------------- fused prep kernel ----------------
// blocks [0,8192): A fragments.  blocks [8192,9728): B fragments.
// A fragment (m16n8k16, row-major A 16x16), lane (g,t):
//   a0={A[g][2t],A[g][2t+1]} a1={A[g+8][..]} a2={A[g][2t+8],..} a3={A[g+8][2t+8],..}
// B fragment (k16 x n8 "col"), lane (g,t):
//   b0={B[2t][g],B[2t+1][g]}  b1={B[2t+8][g],B[2t+9][g]}; chunk c packs ntiles 2c,2c+1.
__global__ void __launch_bounds__(256)
prep_ab(const float* __restrict__ X, const float* __restrict__ Wq,
        const float* __restrict__ Wk, const float* __restrict__ Wv) {
    const int lane = threadIdx.x & 31;
    const int g = lane >> 2, t = lane & 3;
    if (blockIdx.x < 8192) {
        const int tId = blockIdx.x * 8 + (threadIdx.x >> 5);   // 65536 tiles
        const int mt = tId >> 6, kt = tId & 63;
        const int r0 = mt * 16 + g;
        const int c0 = kt * 16 + 2 * t;
        const float2* x0 = reinterpret_cast<const float2*>(X + (size_t)r0 * KDIM + c0);
        const float2* x1 = reinterpret_cast<const float2*>(X + (size_t)(r0 + 8) * KDIM + c0);
        float2 v00 = x0[0], v02 = x0[4];
        float2 v10 = x1[0], v12 = x1[4];
        uint4 o;
        o.x = h2u(v00.x, v00.y);
        o.y = h2u(v10.x, v10.y);
        o.z = h2u(v02.x, v02.y);
        o.w = h2u(v12.x, v12.y);
        g_A[(size_t)tId * 32 + lane] = o;
    } else {
        const int wId = (blockIdx.x - 8192) * 8 + (threadIdx.x >> 5);   // 12288
        const int nb = wId >> 8;          // 0..47
        const int kk = (wId >> 2) & 63;   // ktile16
        const int c = wId & 3;            // chunk
        const int n0 = nb * 64 + (2 * c) * 8 + g;
        const int n1 = n0 + 8;
        const float* W = (n0 < 1024) ? Wq : (n0 < 2048) ? Wk : Wv;
        const int nc0 = n0 & 1023, nc1 = n1 & 1023;
        const int k0 = kk * 16 + 2 * t;
        uint4 o;
        o.x = h2u(W[(size_t)k0 * 1024 + nc0],       W[(size_t)(k0 + 1) * 1024 + nc0]);
        o.y = h2u(W[(size_t)(k0 + 8) * 1024 + nc0], W[(size_t)(k0 + 9) * 1024 + nc0]);
        o.z = h2u(W[(size_t)k0 * 1024 + nc1],       W[(size_t)(k0 + 1) * 1024 + nc1]);
        o.w = h2u(W[(size_t)(k0 + 8) * 1024 + nc1], W[(size_t)(k0 + 9) * 1024 + nc1]);
        g_B[((size_t)(nb * 64 + kk) * 4 + c) * 32 + lane] = o;
    }
}

// ---------------- GEMM ----------------
__global__ void __launch_bounds__(128, 3)
qkv_f16_mma(const float* __restrict__ bq, const float* __restrict__ bk,
            const float* __restrict__ bv, float* __restrict__ out) {
    extern __shared__ char smem[];
    const uint32_t sb = smem_u32(smem);
    const int tid = threadIdx.x;
    const int warp = tid >> 5;
    const int lane = tid & 31;
    const int g = lane >> 2, t = lane & 3;
    const int warpRow = warp >> 1;   // 0..1 (64 rows)
    const int warpCol = warp & 1;    // 0..1 (64 cols)

    const int nblk = blockIdx.x;         // 0..23
    const int mblk = blockIdx.y;         // 0..127
    const int mat = nblk >> 3;
    const int n0w = (nblk & 7) * BN;     // n within matrix
    const int m0 = mblk * BM;
    const int mtile0 = mblk * 8;
    const int nb0 = nblk * 2;            // global 64-col block index
    const float* bias = (mat == 0) ? bq : (mat == 1) ? bk : bv;

    float acc[4][8][4];
#pragma unroll
    for (int i = 0; i < 4; i++)
#pragma unroll
        for (int j = 0; j < 8; j++)
#pragma unroll
            for (int r = 0; r < 4; r++) acc[i][j][r] = 0.0f;

    // A fragment pointer for this warp: advances 64 uint4 per kt.
    // index(mtl, kc, kt) = base + mtl*2048 + kt*64 + kc*32   (uint4 units)
    const uint4* aPtr =
        g_A + ((size_t)(mtile0 + warpRow * 4) * 64) * 32 + lane;

    // B smem: [nbL(2)][kc(2)][c(4)][lane(32)] x 16B per stage (8KB)
    auto load_stage = [&](int s, int kt) {
        const uint32_t bB = sb + s * B_BYTES;
#pragma unroll
        for (int i = 0; i < 4; i++) {   // 512 x 16B
            int chunk = tid + i * 128;
            int b = chunk >> 5, l = chunk & 31;
            int nbL = b >> 3, kc = (b >> 2) & 1, c = b & 3;
            cp16(bB + chunk * 16,
                 g_B + ((size_t)((nb0 + nbL) * 64 + kt * 2 + kc) * 4 + c) * 32 + l);
        }
        asm volatile("cp.async.commit_group;" ::: "memory");
    };

    load_stage(0, 0);
    load_stage(1, 1);
    load_stage(2, 2);

    for (int kt = 0; kt < NKT; kt++) {
        const int s = kt & 3;

        // Issue A-fragment LDGs for this kt before waiting on the B stage:
        // the wait+sync+first-b-LDS window hides most of the L1/L2 latency.
        uint4 af[2][4];
#pragma unroll
        for (int kc = 0; kc < 2; kc++)
#pragma unroll
            for (int mtl = 0; mtl < 4; mtl++)
                af[kc][mtl] = __ldg(aPtr + mtl * 2048 + kc * 32);

        asm volatile("cp.async.wait_group 2;" ::: "memory");
        __syncthreads();
        // Refill buffer (kt+3)&3: its old contents (stage kt-1) were consumed
        // by all warps before the barrier above.
        if (kt + 3 < NKT) load_stage((kt + 3) & 3, kt + 3);

        const char* bP = smem + s * B_BYTES;
#pragma unroll
        for (int kc = 0; kc < 2; kc++) {
#pragma unroll
            for (int c = 0; c < 4; c++) {
                uint4 b = *reinterpret_cast<const uint4*>(
                    bP + (((warpCol * 2 + kc) * 4 + c) * 32 + lane) * 16);
#pragma unroll
                for (int mtl = 0; mtl < 4; mtl++) {
                    mma_f16(acc[mtl][2 * c + 0], af[kc][mtl], b.x, b.y);
                    mma_f16(acc[mtl][2 * c + 1], af[kc][mtl], b.z, b.w);
                }
            }
        }
        aPtr += 64;
    }
    asm volatile("cp.async.wait_group 0;" ::: "memory");

    // ---- epilogue: bias + head-split scatter ----
    float* outm = out + (size_t)mat * OUT_PER_MAT;
#pragma unroll
    for (int mtl = 0; mtl < 4; mtl++) {
#pragma unroll
        for (int rh = 0; rh < 2; rh++) {
            const int row = m0 + warpRow * 64 + mtl * 16 + g + rh * 8;
            const int bb = row >> 12;
            const int sq = row & 4095;
#pragma unroll
            for (int nt = 0; nt < 8; nt++) {
                const int nloc = n0w + warpCol * 64 + nt * 8 + 2 * t;
                const int head = nloc >> 6;
                const int d = nloc & 63;
                const float v0 = acc[mtl][nt][rh * 2 + 0] + bias[nloc];
                const float v1 = acc[mtl][nt][rh * 2 + 1] + bias[nloc + 1];
                const size_t idx = ((size_t)((bb * 16 + head) * 4096 + sq)) * 64 + d;
                *reinterpret_cast<float2*>(outm + idx) = make_float2(v0, v1);
            }
        }
    }
}

// ---------------- launch ----------------
extern "C" void kernel_launch(void* const* d_in, const int* in_sizes, int n_in,
                              void* d_out, int out_size) {
    const float* X  = (const float*)d_in[0];
    const float* Wq = (const float*)d_in[1];
    const float* bq = (const float*)d_in[2];
    const float* Wk = (const float*)d_in[3];
    const float* bk = (const float*)d_in[4];
    const float* Wv = (const float*)d_in[5];
    const float* bv = (const float*)d_in[6];
    float* out = (float*)d_out;

    prep_ab<<<8192 + 1536, 256>>>(X, Wq, Wk, Wv);

    cudaFuncSetAttribute(qkv_f16_mma,
                         cudaFuncAttributeMaxDynamicSharedMemorySize, SMEM_TOTAL);
    qkv_f16_mma<<<dim3(24, 128), 128, SMEM_TOTAL>>>(bq, bk, bv, out);
}